// round 6
// baseline (speedup 1.0000x reference)
#include <cuda_runtime.h>
#include <cstdint>

// Problem constants
#define NB   2
#define SEQ  2048
#define NH   32
#define DH   128
// Tiling
#define BM   128
#define BN   64
#define NTHREADS 512   // 16 warps: (wp 0..7, side 0..1)

// Shared memory byte offsets
#define SM_QP  0                 // packed Q fragments: 8wp x 16ks x 32 lanes x 16B = 64KB
#define SM_KP  65536             // packed K fragments, 32KB
#define SM_VP  98304             // packed V fragments, 32KB
#define SM_PP  131072            // packed P fragments, 32KB
#define SM_SUM 163840            // 256 floats row-sum exchange
#define SMEM_BYTES 164864

static __device__ __forceinline__ float ex2f(float x) {
    float y; asm("ex2.approx.ftz.f32 %0, %1;" : "=f"(y) : "f"(x)); return y;
}
static __device__ __forceinline__ float tf32r(float x) {
    uint32_t y; asm("cvt.rna.tf32.f32 %0, %1;" : "=r"(y) : "f"(x));
    return __uint_as_float(y);
}
// D(16x8,f32) += A(16x8,tf32) * B(8x8,tf32)
static __device__ __forceinline__ void mma8(float& c0, float& c1, float& c2, float& c3,
                                            uint32_t a0, uint32_t a1, uint32_t a2, uint32_t a3,
                                            uint32_t b0, uint32_t b1) {
    asm volatile("mma.sync.aligned.m16n8k8.row.col.f32.tf32.tf32.f32 "
        "{%0,%1,%2,%3}, {%4,%5,%6,%7}, {%8,%9}, {%0,%1,%2,%3};"
        : "+f"(c0), "+f"(c1), "+f"(c2), "+f"(c3)
        : "r"(a0), "r"(a1), "r"(a2), "r"(a3), "r"(b0), "r"(b1));
}

__global__ __launch_bounds__(NTHREADS, 1)
void attn_mma_kernel(const float* __restrict__ qkv,
                     const int* __restrict__ causal_ptr,
                     float* __restrict__ out)
{
    extern __shared__ char smem[];
    float4* Qp  = reinterpret_cast<float4*>(smem + SM_QP);
    float*  QpF = reinterpret_cast<float*>(smem + SM_QP);
    float4* Kp  = reinterpret_cast<float4*>(smem + SM_KP);
    float*  KpF = reinterpret_cast<float*>(smem + SM_KP);
    float4* Vp  = reinterpret_cast<float4*>(smem + SM_VP);
    float*  VpF = reinterpret_cast<float*>(smem + SM_VP);
    float4* Pp  = reinterpret_cast<float4*>(smem + SM_PP);
    float*  SumF = reinterpret_cast<float*>(smem + SM_SUM);

    const int qt   = (gridDim.x - 1) - blockIdx.x;   // heavy (long) q-tiles first
    const int h    = blockIdx.y;
    const int b    = blockIdx.z;
    const int tid  = threadIdx.x;
    const int wid  = tid >> 5;
    const int lane = tid & 31;
    const int wp   = wid & 7;       // q-row group: rows [16wp, 16wp+16)
    const int side = wid >> 3;      // n-split: 0 or 1
    const int g    = lane >> 2;
    const int t    = lane & 3;
    const int c2t  = 2 * t;

    const int causal = *causal_ptr;
    const int q_base = qt * BM;
    const int kt_num = causal ? ((q_base + BM) / BN) : (SEQ / BN);

    // ---- pack Q fragments directly gmem -> smem (scaled + tf32, XOR-swizzled) ----
    const float qf = 0.08838834764831845f * 1.4426950408889634f; // 1/sqrt(D)*log2(e)
    {
        const float* qg = qkv + (((size_t)b * SEQ + q_base) * 3 * NH + h) * DH;
        const size_t qstride = (size_t)3 * NH * DH;
        for (int i = tid; i < BM * (DH / 4); i += NTHREADS) {
            int r = i >> 5, c = i & 31;
            float4 v = *(reinterpret_cast<const float4*>(qg + (size_t)r * qstride) + c);
            int wpr = r >> 4, gg = r & 7, pairsel = (r >> 3) & 1;
            int ks = c >> 1, hi = c & 1;
            int key = ks & 7;
            int base4 = (wpr * 16 + ks) * 32;
            int comp = hi * 2 + pairsel;
            QpF[(base4 + ((gg * 4 + 0) ^ key)) * 4 + comp] = tf32r(v.x * qf);
            QpF[(base4 + ((gg * 4 + 1) ^ key)) * 4 + comp] = tf32r(v.y * qf);
            QpF[(base4 + ((gg * 4 + 2) ^ key)) * 4 + comp] = tf32r(v.z * qf);
            QpF[(base4 + ((gg * 4 + 3) ^ key)) * 4 + comp] = tf32r(v.w * qf);
        }
    }

    const float* kg = qkv + ((size_t)b * SEQ * 3 * NH + (size_t)1 * NH + h) * DH;
    const float* vg = qkv + ((size_t)b * SEQ * 3 * NH + (size_t)2 * NH + h) * DH;
    const size_t kvstride = (size_t)3 * NH * DH;

    float oacc[8][4];                // this side's 64 output cols (8 n-tiles)
    #pragma unroll
    for (int n = 0; n < 8; n++)
        #pragma unroll
        for (int j = 0; j < 4; j++) oacc[n][j] = 0.0f;
    float sumA = 0.0f, sumB = 0.0f;  // partial (this side's 32 columns per tile)

    const int rowA = q_base + 16 * wp + g;
    const int rowB = rowA + 8;

    for (int kt = 0; kt < kt_num; kt++) {
        const int k_base = kt * BN;

        __syncthreads();   // prev iteration done reading Kp/Vp/Pp (covers Qp pack 1st iter)

        // ---- stage K tile (ks-XOR swizzled fragment layout) ----
        for (int i = tid; i < BN * (DH / 4); i += NTHREADS) {
            int n = i >> 5, c = i & 31;
            float4 v = *(reinterpret_cast<const float4*>(kg + (size_t)(k_base + n) * kvstride) + c);
            int ks = c >> 1, slot = c & 1;
            int ntp = n >> 4, gg = n & 7, pairsel = (n >> 3) & 1;
            int base4 = (ks * 4 + ntp) * 32;
            int comp  = pairsel * 2 + slot;
            int key   = ks & 7;
            KpF[(base4 + ((gg * 4 + 0) ^ key)) * 4 + comp] = tf32r(v.x);
            KpF[(base4 + ((gg * 4 + 1) ^ key)) * 4 + comp] = tf32r(v.y);
            KpF[(base4 + ((gg * 4 + 2) ^ key)) * 4 + comp] = tf32r(v.z);
            KpF[(base4 + ((gg * 4 + 3) ^ key)) * 4 + comp] = tf32r(v.w);
        }
        // ---- stage V tile (ntp-XOR swizzled fragment layout) ----
        for (int i = tid; i < BN * (DH / 4); i += NTHREADS) {
            int s = i >> 5, c = i & 31;
            float4 v = *(reinterpret_cast<const float4*>(vg + (size_t)(k_base + s) * kvstride) + c);
            int ks = s >> 3, slot = ((s & 7) >= 4) ? 1 : 0, tt = s & 3;
            int ntp = c >> 2, pairsel = (c >> 1) & 1;
            int base4 = (ks * 8 + ntp) * 32;
            int comp  = pairsel * 2 + slot;
            int x0    = (c & 1) * 16 + tt;
            VpF[(base4 + ((x0 + 0)  ^ ntp)) * 4 + comp] = tf32r(v.x);
            VpF[(base4 + ((x0 + 4)  ^ ntp)) * 4 + comp] = tf32r(v.y);
            VpF[(base4 + ((x0 + 8)  ^ ntp)) * 4 + comp] = tf32r(v.z);
            VpF[(base4 + ((x0 + 12) ^ ntp)) * 4 + comp] = tf32r(v.w);
        }
        __syncthreads();

        // ---- MMA1: this side's 4 n-tiles, 16 k-steps ----
        float sacc[4][4];
        #pragma unroll
        for (int n = 0; n < 4; n++)
            #pragma unroll
            for (int j = 0; j < 4; j++) sacc[n][j] = 0.0f;

        #pragma unroll
        for (int ks = 0; ks < 16; ks++) {
            const int xl = lane ^ (ks & 7);
            float4 aq  = Qp[(wp * 16 + ks) * 32 + xl];
            float4 b01 = Kp[(ks * 4 + 2 * side) * 32 + xl];
            float4 b23 = Kp[(ks * 4 + 2 * side + 1) * 32 + xl];
            const uint32_t a0 = __float_as_uint(aq.x), a1 = __float_as_uint(aq.y);
            const uint32_t a2 = __float_as_uint(aq.z), a3 = __float_as_uint(aq.w);
            mma8(sacc[0][0], sacc[0][1], sacc[0][2], sacc[0][3], a0, a1, a2, a3, __float_as_uint(b01.x), __float_as_uint(b01.y));
            mma8(sacc[1][0], sacc[1][1], sacc[1][2], sacc[1][3], a0, a1, a2, a3, __float_as_uint(b01.z), __float_as_uint(b01.w));
            mma8(sacc[2][0], sacc[2][1], sacc[2][2], sacc[2][3], a0, a1, a2, a3, __float_as_uint(b23.x), __float_as_uint(b23.y));
            mma8(sacc[3][0], sacc[3][1], sacc[3][2], sacc[3][3], a0, a1, a2, a3, __float_as_uint(b23.z), __float_as_uint(b23.w));
        }

        // ---- softmax + pack P fragments (this side's columns) ----
        const bool do_mask = causal && (k_base + BN - 1 > q_base);
        const int l0 = g * 4 + (c2t & 3);
        const int l1 = g * 4 + ((c2t + 1) & 3);
        const int h0 = (c2t >= 4) ? 2 : 0;

        #pragma unroll
        for (int j = 0; j < 4; j++) {
            const int nt = 4 * side + j;
            float p0 = ex2f(sacc[j][0]);
            float p1 = ex2f(sacc[j][1]);
            float p2 = ex2f(sacc[j][2]);
            float p3 = ex2f(sacc[j][3]);
            if (do_mask) {
                const int cg = k_base + nt * 8 + c2t;
                if (cg     > rowA) p0 = 0.0f;
                if (cg + 1 > rowA) p1 = 0.0f;
                if (cg     > rowB) p2 = 0.0f;
                if (cg + 1 > rowB) p3 = 0.0f;
            }
            sumA += p0 + p1;
            sumB += p2 + p3;
            float2* pv2 = reinterpret_cast<float2*>(reinterpret_cast<float*>(Pp) + (wp * 8 + nt) * 128);
            pv2[(l0 * 4 + h0) >> 1] = make_float2(tf32r(p0), tf32r(p2));
            pv2[(l1 * 4 + h0) >> 1] = make_float2(tf32r(p1), tf32r(p3));
        }
        __syncthreads();

        // ---- MMA2: O(this side's 64 cols) += P * V  (8 k-steps x 4 ntp) ----
        #pragma unroll
        for (int ks = 0; ks < 8; ks++) {
            float4 af = Pp[(wp * 8 + ks) * 32 + lane];
            const uint32_t a0 = __float_as_uint(af.x), a1 = __float_as_uint(af.y);
            const uint32_t a2 = __float_as_uint(af.z), a3 = __float_as_uint(af.w);
            #pragma unroll
            for (int l = 0; l < 4; l++) {
                const int ntp = side * 4 + l;
                float4 bv = Vp[(ks * 8 + ntp) * 32 + (lane ^ ntp)];
                mma8(oacc[2 * l][0], oacc[2 * l][1], oacc[2 * l][2], oacc[2 * l][3],
                     a0, a1, a2, a3, __float_as_uint(bv.x), __float_as_uint(bv.y));
                mma8(oacc[2 * l + 1][0], oacc[2 * l + 1][1], oacc[2 * l + 1][2], oacc[2 * l + 1][3],
                     a0, a1, a2, a3, __float_as_uint(bv.z), __float_as_uint(bv.w));
            }
        }
    }

    // ---- combine row sums: quad reduce, then cross-side via smem ----
    sumA += __shfl_xor_sync(0xffffffffu, sumA, 1);
    sumA += __shfl_xor_sync(0xffffffffu, sumA, 2);
    sumB += __shfl_xor_sync(0xffffffffu, sumB, 1);
    sumB += __shfl_xor_sync(0xffffffffu, sumB, 2);
    if (t == 0) {
        SumF[side * 128 + 16 * wp + g]     = sumA;
        SumF[side * 128 + 16 * wp + g + 8] = sumB;
    }
    __syncthreads();
    const int rlA = 16 * wp + g;
    const float invA = 1.0f / (SumF[rlA] + SumF[128 + rlA]);
    const float invB = 1.0f / (SumF[rlA + 8] + SumF[128 + rlA + 8]);

    // ---- normalize and write this side's 64 columns ----
    float* opA = out + (((size_t)b * SEQ + rowA) * NH + h) * DH + side * 64;
    float* opB = out + (((size_t)b * SEQ + rowB) * NH + h) * DH + side * 64;
    #pragma unroll
    for (int nt = 0; nt < 8; nt++) {
        const int col = nt * 8 + c2t;
        float2 va = make_float2(oacc[nt][0] * invA, oacc[nt][1] * invA);
        float2 vb = make_float2(oacc[nt][2] * invB, oacc[nt][3] * invB);
        *reinterpret_cast<float2*>(opA + col) = va;
        *reinterpret_cast<float2*>(opB + col) = vb;
    }
}

extern "C" void kernel_launch(void* const* d_in, const int* in_sizes, int n_in,
                              void* d_out, int out_size)
{
    const float* qkv    = (const float*)d_in[0];
    const int*   causal = (const int*)d_in[1];
    float*       out    = (float*)d_out;

    cudaFuncSetAttribute(attn_mma_kernel,
                         cudaFuncAttributeMaxDynamicSharedMemorySize, SMEM_BYTES);

    dim3 grid(SEQ / BM, NH, NB);
    attn_mma_kernel<<<grid, NTHREADS, SMEM_BYTES>>>(qkv, causal, out);
}

// round 7
// speedup vs baseline: 1.4943x; 1.4943x over previous
#include <cuda_runtime.h>
#include <cstdint>

// Problem constants
#define NB   2
#define SEQ  2048
#define NH   32
#define DH   128
// Tiling
#define BM   128
#define BN   64
#define NTHREADS 256   // 8 warps; warp w owns q rows [16w, 16w+16)

// Shared memory layout (bytes)
// raw double buffers: buf{0,1} x (K[64][128]f32 , V[64][128]f32)
#define SM_RAW      0
#define RAW_BUFSZ   65536                 // 32KB K + 32KB V
#define SM_KP       131072                // packed K fragments, 32KB
#define SM_VP       163840                // packed V fragments, 32KB
#define SM_PP       196608                // packed P fragments, 32KB
#define SM_QSTAGE   SM_KP                 // Q staging aliased over packed region (pre-loop only)
#define SMEM_BYTES  229376

static __device__ __forceinline__ uint32_t smem_u32(const void* p) {
    uint32_t a;
    asm("{ .reg .u64 t; cvta.to.shared.u64 t, %1; cvt.u32.u64 %0, t; }" : "=r"(a) : "l"(p));
    return a;
}
static __device__ __forceinline__ void cpa16(uint32_t saddr, const void* g) {
    asm volatile("cp.async.ca.shared.global [%0], [%1], 16;" :: "r"(saddr), "l"(g));
}
static __device__ __forceinline__ float ex2f(float x) {
    float y; asm("ex2.approx.ftz.f32 %0, %1;" : "=f"(y) : "f"(x)); return y;
}
static __device__ __forceinline__ float tf32r(float x) {
    uint32_t y; asm("cvt.rna.tf32.f32 %0, %1;" : "=r"(y) : "f"(x));
    return __uint_as_float(y);
}
// D(16x8,f32) += A(16x8,tf32) * B(8x8,tf32)
static __device__ __forceinline__ void mma8(float& c0, float& c1, float& c2, float& c3,
                                            uint32_t a0, uint32_t a1, uint32_t a2, uint32_t a3,
                                            uint32_t b0, uint32_t b1) {
    asm volatile("mma.sync.aligned.m16n8k8.row.col.f32.tf32.tf32.f32 "
        "{%0,%1,%2,%3}, {%4,%5,%6,%7}, {%8,%9}, {%0,%1,%2,%3};"
        : "+f"(c0), "+f"(c1), "+f"(c2), "+f"(c3)
        : "r"(a0), "r"(a1), "r"(a2), "r"(a3), "r"(b0), "r"(b1));
}

__global__ __launch_bounds__(NTHREADS, 1)
void attn_mma_kernel(const float* __restrict__ qkv,
                     const int* __restrict__ causal_ptr,
                     float* __restrict__ out)
{
    extern __shared__ char smem[];
    const uint32_t sbase = smem_u32(smem);
    float4* Kp  = reinterpret_cast<float4*>(smem + SM_KP);
    float*  KpF = reinterpret_cast<float*>(smem + SM_KP);
    float4* Vp  = reinterpret_cast<float4*>(smem + SM_VP);
    float*  VpF = reinterpret_cast<float*>(smem + SM_VP);
    float4* Pp  = reinterpret_cast<float4*>(smem + SM_PP);
    float*  Qs  = reinterpret_cast<float*>(smem + SM_QSTAGE);   // [128][132], pre-loop only

    const int qt   = (gridDim.x - 1) - blockIdx.x;   // heavy (long) q-tiles first
    const int h    = blockIdx.y;
    const int b    = blockIdx.z;
    const int tid  = threadIdx.x;
    const int w    = tid >> 5;
    const int lane = tid & 31;
    const int g    = lane >> 2;
    const int t    = lane & 3;
    const int c2t  = 2 * t;

    const int causal = *causal_ptr;
    const int q_base = qt * BM;
    const int kt_num = causal ? ((q_base + BM) / BN) : (SEQ / BN);

    const float* kg = qkv + ((size_t)b * SEQ * 3 * NH + (size_t)1 * NH + h) * DH;
    const float* vg = qkv + ((size_t)b * SEQ * 3 * NH + (size_t)2 * NH + h) * DH;
    const size_t kvstride = (size_t)3 * NH * DH;

    // my fixed slice of staging work: 8 (row, col4) pairs
    const int sr = tid >> 5;        // base row 0..7 (rows sr, sr+8, ..., sr+56)
    const int sc = tid & 31;        // float4 column 0..31

    // ---- prologue: async-fetch tile 0 into raw buffer 0 ----
    {
        const uint32_t rawK = sbase + SM_RAW;
        const uint32_t rawV = rawK + 32768;
        #pragma unroll
        for (int u = 0; u < 8; u++) {
            const int r = sr + 8 * u;
            cpa16(rawK + (uint32_t)(r * 128 + sc * 4) * 4, kg + (size_t)r * kvstride + sc * 4);
            cpa16(rawV + (uint32_t)(r * 128 + sc * 4) * 4, vg + (size_t)r * kvstride + sc * 4);
        }
        asm volatile("cp.async.commit_group;" ::: "memory");
    }

    // ---- stage Q (scaled + tf32) into aliased smem, then lift to registers ----
    const float qf = 0.08838834764831845f * 1.4426950408889634f; // 1/sqrt(D)*log2(e)
    {
        const float* qg = qkv + (((size_t)b * SEQ + q_base) * 3 * NH + h) * DH;
        const size_t qstride = (size_t)3 * NH * DH;
        #pragma unroll
        for (int u = 0; u < 16; u++) {
            const int r = sr + 8 * u;   // rows 0..127
            float4 v = *(reinterpret_cast<const float4*>(qg + (size_t)r * qstride) + sc);
            Qs[r * 132 + sc * 4 + 0] = tf32r(v.x * qf);
            Qs[r * 132 + sc * 4 + 1] = tf32r(v.y * qf);
            Qs[r * 132 + sc * 4 + 2] = tf32r(v.z * qf);
            Qs[r * 132 + sc * 4 + 3] = tf32r(v.w * qf);
        }
    }
    __syncthreads();

    uint32_t qa[16][4];   // A fragments of Q for all 16 k-steps
    {
        const float* r0 = &Qs[(16 * w + g) * 132];
        const float* r1 = &Qs[(16 * w + g + 8) * 132];
        #pragma unroll
        for (int ks = 0; ks < 16; ks++) {
            qa[ks][0] = __float_as_uint(r0[8 * ks + t]);
            qa[ks][1] = __float_as_uint(r1[8 * ks + t]);
            qa[ks][2] = __float_as_uint(r0[8 * ks + t + 4]);
            qa[ks][3] = __float_as_uint(r1[8 * ks + t + 4]);
        }
    }

    float oacc[16][4];
    #pragma unroll
    for (int n = 0; n < 16; n++)
        #pragma unroll
        for (int j = 0; j < 4; j++) oacc[n][j] = 0.0f;
    float sumA = 0.0f, sumB = 0.0f;

    const int rowA = q_base + 16 * w + g;
    const int rowB = rowA + 8;

    for (int kt = 0; kt < kt_num; kt++) {
        const int k_base = kt * BN;

        // all warps done with previous compute (Kp/Vp/Pp) and previous repack (raw[nxt])
        __syncthreads();

        // ---- issue async fetch of next tile into the other raw buffer ----
        {
            const int nk = (kt + 1 < kt_num ? kt + 1 : kt_num - 1) * BN;
            const uint32_t rawK = sbase + SM_RAW + ((kt + 1) & 1) * RAW_BUFSZ;
            const uint32_t rawV = rawK + 32768;
            #pragma unroll
            for (int u = 0; u < 8; u++) {
                const int r = sr + 8 * u;
                cpa16(rawK + (uint32_t)(r * 128 + sc * 4) * 4, kg + (size_t)(nk + r) * kvstride + sc * 4);
                cpa16(rawV + (uint32_t)(r * 128 + sc * 4) * 4, vg + (size_t)(nk + r) * kvstride + sc * 4);
            }
            asm volatile("cp.async.commit_group;" ::: "memory");
        }
        // current tile's group (issued last iteration) must be complete
        asm volatile("cp.async.wait_group 1;" ::: "memory");

        // ---- repack raw -> fragment layouts (same swizzles as proven R5) ----
        {
            const float4* rawK4 = reinterpret_cast<const float4*>(smem + SM_RAW + (kt & 1) * RAW_BUFSZ);
            const float4* rawV4 = rawK4 + 32768 / 16;
            #pragma unroll
            for (int u = 0; u < 8; u++) {
                const int n = sr + 8 * u, c = sc;
                float4 v = rawK4[n * 32 + c];
                int ks = c >> 1, slot = c & 1;
                int ntp = n >> 4, gg = n & 7, pairsel = (n >> 3) & 1;
                int base4 = (ks * 4 + ntp) * 32;
                int comp  = pairsel * 2 + slot;
                int key   = ks & 7;
                KpF[(base4 + ((gg * 4 + 0) ^ key)) * 4 + comp] = tf32r(v.x);
                KpF[(base4 + ((gg * 4 + 1) ^ key)) * 4 + comp] = tf32r(v.y);
                KpF[(base4 + ((gg * 4 + 2) ^ key)) * 4 + comp] = tf32r(v.z);
                KpF[(base4 + ((gg * 4 + 3) ^ key)) * 4 + comp] = tf32r(v.w);
            }
            #pragma unroll
            for (int u = 0; u < 8; u++) {
                const int s = sr + 8 * u, c = sc;
                float4 v = rawV4[s * 32 + c];
                int ks = s >> 3, slot = ((s & 7) >= 4) ? 1 : 0, tt = s & 3;
                int ntp = c >> 2, pairsel = (c >> 1) & 1;
                int base4 = (ks * 8 + ntp) * 32;
                int comp  = pairsel * 2 + slot;
                int x0    = (c & 1) * 16 + tt;
                VpF[(base4 + ((x0 + 0)  ^ ntp)) * 4 + comp] = tf32r(v.x);
                VpF[(base4 + ((x0 + 4)  ^ ntp)) * 4 + comp] = tf32r(v.y);
                VpF[(base4 + ((x0 + 8)  ^ ntp)) * 4 + comp] = tf32r(v.z);
                VpF[(base4 + ((x0 + 12) ^ ntp)) * 4 + comp] = tf32r(v.w);
            }
        }
        __syncthreads();

        // ---- MMA1: S = Q * K^T   (16 k-steps x 8 n-tiles) ----
        float sacc[8][4];
        #pragma unroll
        for (int n = 0; n < 8; n++)
            #pragma unroll
            for (int j = 0; j < 4; j++) sacc[n][j] = 0.0f;

        #pragma unroll
        for (int ks = 0; ks < 16; ks++) {
            const int xl = lane ^ (ks & 7);
            float4 b01 = Kp[(ks * 4 + 0) * 32 + xl];
            float4 b23 = Kp[(ks * 4 + 1) * 32 + xl];
            float4 b45 = Kp[(ks * 4 + 2) * 32 + xl];
            float4 b67 = Kp[(ks * 4 + 3) * 32 + xl];
            mma8(sacc[0][0], sacc[0][1], sacc[0][2], sacc[0][3], qa[ks][0], qa[ks][1], qa[ks][2], qa[ks][3], __float_as_uint(b01.x), __float_as_uint(b01.y));
            mma8(sacc[1][0], sacc[1][1], sacc[1][2], sacc[1][3], qa[ks][0], qa[ks][1], qa[ks][2], qa[ks][3], __float_as_uint(b01.z), __float_as_uint(b01.w));
            mma8(sacc[2][0], sacc[2][1], sacc[2][2], sacc[2][3], qa[ks][0], qa[ks][1], qa[ks][2], qa[ks][3], __float_as_uint(b23.x), __float_as_uint(b23.y));
            mma8(sacc[3][0], sacc[3][1], sacc[3][2], sacc[3][3], qa[ks][0], qa[ks][1], qa[ks][2], qa[ks][3], __float_as_uint(b23.z), __float_as_uint(b23.w));
            mma8(sacc[4][0], sacc[4][1], sacc[4][2], sacc[4][3], qa[ks][0], qa[ks][1], qa[ks][2], qa[ks][3], __float_as_uint(b45.x), __float_as_uint(b45.y));
            mma8(sacc[5][0], sacc[5][1], sacc[5][2], sacc[5][3], qa[ks][0], qa[ks][1], qa[ks][2], qa[ks][3], __float_as_uint(b45.z), __float_as_uint(b45.w));
            mma8(sacc[6][0], sacc[6][1], sacc[6][2], sacc[6][3], qa[ks][0], qa[ks][1], qa[ks][2], qa[ks][3], __float_as_uint(b67.x), __float_as_uint(b67.y));
            mma8(sacc[7][0], sacc[7][1], sacc[7][2], sacc[7][3], qa[ks][0], qa[ks][1], qa[ks][2], qa[ks][3], __float_as_uint(b67.z), __float_as_uint(b67.w));
        }

        // ---- softmax + pack P fragments (intra-warp exchange only) ----
        const bool do_mask = causal && (k_base + BN - 1 > q_base);
        const int l0 = g * 4 + (c2t & 3);
        const int l1 = g * 4 + ((c2t + 1) & 3);
        const int h0 = (c2t >= 4) ? 2 : 0;

        #pragma unroll
        for (int nt = 0; nt < 8; nt++) {
            float p0 = ex2f(sacc[nt][0]);
            float p1 = ex2f(sacc[nt][1]);
            float p2 = ex2f(sacc[nt][2]);
            float p3 = ex2f(sacc[nt][3]);
            if (do_mask) {
                const int cg = k_base + nt * 8 + c2t;
                if (cg     > rowA) p0 = 0.0f;
                if (cg + 1 > rowA) p1 = 0.0f;
                if (cg     > rowB) p2 = 0.0f;
                if (cg + 1 > rowB) p3 = 0.0f;
            }
            sumA += p0 + p1;
            sumB += p2 + p3;
            float2* pv2 = reinterpret_cast<float2*>(reinterpret_cast<float*>(Pp) + (w * 8 + nt) * 128);
            pv2[(l0 * 4 + h0) >> 1] = make_float2(tf32r(p0), tf32r(p2));
            pv2[(l1 * 4 + h0) >> 1] = make_float2(tf32r(p1), tf32r(p3));
        }
        __syncwarp();   // P rows (w*8+*) produced and consumed by this warp only

        // ---- MMA2: O += P * V   (8 k-steps x 16 n-tiles) ----
        #pragma unroll
        for (int ks = 0; ks < 8; ks++) {
            float4 af = Pp[(w * 8 + ks) * 32 + lane];
            const uint32_t a0 = __float_as_uint(af.x), a1 = __float_as_uint(af.y);
            const uint32_t a2 = __float_as_uint(af.z), a3 = __float_as_uint(af.w);
            #pragma unroll
            for (int ntp = 0; ntp < 8; ntp++) {
                float4 bv = Vp[(ks * 8 + ntp) * 32 + (lane ^ ntp)];
                mma8(oacc[2 * ntp][0], oacc[2 * ntp][1], oacc[2 * ntp][2], oacc[2 * ntp][3],
                     a0, a1, a2, a3, __float_as_uint(bv.x), __float_as_uint(bv.y));
                mma8(oacc[2 * ntp + 1][0], oacc[2 * ntp + 1][1], oacc[2 * ntp + 1][2], oacc[2 * ntp + 1][3],
                     a0, a1, a2, a3, __float_as_uint(bv.z), __float_as_uint(bv.w));
            }
        }
    }
    asm volatile("cp.async.wait_group 0;" ::: "memory");

    // ---- reduce row sums across the quad, normalize, write out ----
    sumA += __shfl_xor_sync(0xffffffffu, sumA, 1);
    sumA += __shfl_xor_sync(0xffffffffu, sumA, 2);
    sumB += __shfl_xor_sync(0xffffffffu, sumB, 1);
    sumB += __shfl_xor_sync(0xffffffffu, sumB, 2);
    const float invA = 1.0f / sumA;
    const float invB = 1.0f / sumB;

    float* opA = out + (((size_t)b * SEQ + rowA) * NH + h) * DH;
    float* opB = out + (((size_t)b * SEQ + rowB) * NH + h) * DH;
    #pragma unroll
    for (int nt = 0; nt < 16; nt++) {
        const int col = nt * 8 + c2t;
        float2 va = make_float2(oacc[nt][0] * invA, oacc[nt][1] * invA);
        float2 vb = make_float2(oacc[nt][2] * invB, oacc[nt][3] * invB);
        *reinterpret_cast<float2*>(opA + col) = va;
        *reinterpret_cast<float2*>(opB + col) = vb;
    }
}

extern "C" void kernel_launch(void* const* d_in, const int* in_sizes, int n_in,
                              void* d_out, int out_size)
{
    const float* qkv    = (const float*)d_in[0];
    const int*   causal = (const int*)d_in[1];
    float*       out    = (float*)d_out;

    cudaFuncSetAttribute(attn_mma_kernel,
                         cudaFuncAttributeMaxDynamicSharedMemorySize, SMEM_BYTES);

    dim3 grid(SEQ / BM, NH, NB);
    attn_mma_kernel<<<grid, NTHREADS, SMEM_BYTES>>>(qkv, causal, out);
}